// round 12
// baseline (speedup 1.0000x reference)
#include <cuda_runtime.h>
#include <cuda_bf16.h>

// S4D via Vandermonde factorization: l = 64q + r,
//   out[h, 64q+r] = sum_n Re( u_n * W_n^q * w_n^r ),  W = w^64
// Register-tiled real-part matmul (one packed f32x2 fma per (n, output)),
// SOFTWARE-PIPELINED: P/Q for iteration n+1 prefetched into a second register
// buffer while iteration n's 32 FFMA2s drain (96 pipe-cyc at rt=3 covers the
// 29-cyc LDS latency). Zero-padded row NH so the prefetch never branches.

#define HH      1024
#define NH      32
#define LL      4096
#define THREADS 128
#define NQ      64
#define NR      64
#define NROW    (NH + 1)    // +1 zero pad row for prefetch overrun
#define QSTR    68          // smem row stride in float2 (16B-aligned)
#define TQ      8           // q-tile per thread
#define TR      4           // r-tile per thread

#define TWO_PI      6.283185307179586f
#define INV_TWO_PI  0.15915494309189535f

union F2U { float2 f; unsigned long long u; };

__device__ __forceinline__ float2 f2_fma(float2 a, float2 b, float2 c) {
    F2U A, B, C, D; A.f = a; B.f = b; C.f = c;
    asm("fma.rn.f32x2 %0, %1, %2, %3;" : "=l"(D.u) : "l"(A.u), "l"(B.u), "l"(C.u));
    return D.f;
}

__global__ __launch_bounds__(THREADS)
void s4d_kernel(const float* __restrict__ C_param,     // (H, 32, 2)
                const float* __restrict__ log_dt,      // (H,)
                const float* __restrict__ log_A_real,  // (H, 32)
                const float* __restrict__ A_imag,      // (H, 32)
                float* __restrict__ out)               // (H, L)
{
    __shared__ float2 P_s[NROW][QSTR];    // (Re(u*W^q), -Im(u*W^q))
    __shared__ float2 Q_s[NROW][QSTR];    // (Re(w^r),  Im(w^r))
    __shared__ float s_re[NH], s_turn[NH], s_wr[NH], s_wi[NH];
    __shared__ float s_ur[NH], s_ui[NH], s_Wr[NH], s_Wi[NH];

    const int h   = blockIdx.x;
    const int tid = threadIdx.x;

    // ---- per-(h,n) parameters (one warp; accurate libm) ----
    if (tid < NH) {
        const int n  = tid;
        const int hn = h * NH + n;
        float dt = expf(log_dt[h]);
        float Ar = -expf(log_A_real[hn]);
        float Ai = A_imag[hn];
        float re = Ar * dt;                          // Re(dtA) (<0)
        float im = Ai * dt;                          // Im(dtA)
        float er = expf(re);
        float si, co; sincosf(im, &si, &co);
        float wr = er * co, wi = er * si;            // w = exp(dtA)
        // u = 2*C*(w-1)/A
        float numr = wr - 1.0f, numi = wi;
        float invd = 1.0f / fmaf(Ar, Ar, Ai * Ai);
        float tr = (numr * Ar + numi * Ai) * invd;
        float ti = (numi * Ar - numr * Ai) * invd;
        float Cr = C_param[2 * hn + 0];
        float Ci = C_param[2 * hn + 1];
        float ur = 2.0f * (Cr * tr - Ci * ti);
        float ui = 2.0f * (Cr * ti + Ci * tr);
        float turn = im * INV_TWO_PI;
        // W = w^64 via turn trick
        float amp64 = expf(64.0f * re);
        float t64   = turn * 64.0f;
        float f64   = t64 - truncf(t64);
        float s64, c64; __sincosf(f64 * TWO_PI, &s64, &c64);
        s_re[n]   = re;   s_turn[n] = turn;
        s_wr[n]   = wr;   s_wi[n]   = wi;
        s_ur[n]   = ur;   s_ui[n]   = ui;
        s_Wr[n]   = amp64 * c64;  s_Wi[n] = amp64 * s64;
    }
    // zero pad row NH (read by the last prefetch, never used)
    if (tid < NQ) {
        P_s[NH][tid] = make_float2(0.0f, 0.0f);
        Q_s[NH][tid] = make_float2(0.0f, 0.0f);
    }
    __syncthreads();

    // ---- generate P and Q tiles: thread (n = tid>>2, j = tid&3) ----
    {
        const int gn = tid >> 2;
        const int gj = tid & 3;
        const float re = s_re[gn], tn = s_turn[gn];

        // Q[n][r] = w^r for r = 16j .. 16j+15
        {
            const float wr = s_wr[gn], wi = s_wi[gn];
            float r0f  = (float)(16 * gj);
            float amp  = __expf(re * r0f);
            float turns = tn * r0f;
            float frac  = turns - truncf(turns);
            float si, co; __sincosf(frac * TWO_PI, &si, &co);
            float zr = amp * co, zi = amp * si;
            #pragma unroll
            for (int i = 0; i < 16; i++) {
                Q_s[gn][16 * gj + i] = make_float2(zr, zi);
                float nzr = zr * wr - zi * wi;
                float nzi = zr * wi + zi * wr;
                zr = nzr; zi = nzi;
            }
        }
        // P[n][q] = u * W^q for q = 16j .. 16j+15  (stored as (pr, -pi))
        {
            const float Wr = s_Wr[gn], Wi = s_Wi[gn];
            const float ur = s_ur[gn], ui = s_ui[gn];
            float l0f  = (float)(1024 * gj);          // 64 * 16j
            float amp  = __expf(re * l0f);
            float turns = tn * l0f;
            float frac  = turns - truncf(turns);
            float si, co; __sincosf(frac * TWO_PI, &si, &co);
            float zr = amp * co, zi = amp * si;       // w^{64*16j}
            float pr = ur * zr - ui * zi;
            float pi = ur * zi + ui * zr;
            #pragma unroll
            for (int i = 0; i < 16; i++) {
                P_s[gn][16 * gj + i] = make_float2(pr, -pi);
                float npr = pr * Wr - pi * Wi;
                float npi = pr * Wi + pi * Wr;
                pr = npr; pi = npi;
            }
        }
    }
    __syncthreads();

    // ---- main: software-pipelined register-tiled real-part matmul ----
    const int q0 = (tid >> 4) << 3;     // 8 q-tiles of 8
    const int r0 = (tid & 15) << 2;     // 16 r-tiles of 4

#define LOADP(dst, nn) do {                                                 \
        float4 t0 = *reinterpret_cast<const float4*>(&P_s[nn][q0 + 0]);     \
        float4 t1 = *reinterpret_cast<const float4*>(&P_s[nn][q0 + 2]);     \
        float4 t2 = *reinterpret_cast<const float4*>(&P_s[nn][q0 + 4]);     \
        float4 t3 = *reinterpret_cast<const float4*>(&P_s[nn][q0 + 6]);     \
        dst[0] = make_float2(t0.x, t0.y); dst[1] = make_float2(t0.z, t0.w); \
        dst[2] = make_float2(t1.x, t1.y); dst[3] = make_float2(t1.z, t1.w); \
        dst[4] = make_float2(t2.x, t2.y); dst[5] = make_float2(t2.z, t2.w); \
        dst[6] = make_float2(t3.x, t3.y); dst[7] = make_float2(t3.z, t3.w); \
    } while (0)

#define LOADQ(dst, nn) do {                                                 \
        float4 t0 = *reinterpret_cast<const float4*>(&Q_s[nn][r0 + 0]);     \
        float4 t1 = *reinterpret_cast<const float4*>(&Q_s[nn][r0 + 2]);     \
        dst[0] = make_float2(t0.x, t0.y); dst[1] = make_float2(t0.z, t0.w); \
        dst[2] = make_float2(t1.x, t1.y); dst[3] = make_float2(t1.z, t1.w); \
    } while (0)

#define FMAS(P, Q) do {                                                     \
        _Pragma("unroll")                                                   \
        for (int qi = 0; qi < TQ; qi++)                                     \
            _Pragma("unroll")                                               \
            for (int ri = 0; ri < TR; ri++)                                 \
                acc[qi][ri] = f2_fma(P[qi], Q[ri], acc[qi][ri]);            \
    } while (0)

    float2 acc[TQ][TR];
    #pragma unroll
    for (int qi = 0; qi < TQ; qi++)
        #pragma unroll
        for (int ri = 0; ri < TR; ri++)
            acc[qi][ri] = make_float2(0.0f, 0.0f);

    float2 Pa[TQ], Qa[TR], Pb[TQ], Qb[TR];
    LOADP(Pa, 0); LOADQ(Qa, 0);

    #pragma unroll 1
    for (int n = 0; n < NH; n += 2) {
        LOADP(Pb, n + 1); LOADQ(Qb, n + 1);   // prefetch while A drains
        FMAS(Pa, Qa);
        LOADP(Pa, n + 2); LOADQ(Qa, n + 2);   // n+2 == NH hits zero pad row
        FMAS(Pb, Qb);
    }

    // ---- epilogue: out[h, 64*(q0+qi) + r0 + ri] = acc.x + acc.y ----
    float* orow = out + (size_t)h * LL + r0;
    #pragma unroll
    for (int qi = 0; qi < TQ; qi++) {
        float4 o = make_float4(acc[qi][0].x + acc[qi][0].y,
                               acc[qi][1].x + acc[qi][1].y,
                               acc[qi][2].x + acc[qi][2].y,
                               acc[qi][3].x + acc[qi][3].y);
        *reinterpret_cast<float4*>(orow + (q0 + qi) * NR) = o;
    }
}

extern "C" void kernel_launch(void* const* d_in, const int* in_sizes, int n_in,
                              void* d_out, int out_size) {
    const float* C_param    = (const float*)d_in[0];
    const float* log_dt     = (const float*)d_in[1];
    const float* log_A_real = (const float*)d_in[2];
    const float* A_imag     = (const float*)d_in[3];
    float* out = (float*)d_out;

    s4d_kernel<<<HH, THREADS>>>(C_param, log_dt, log_A_real, A_imag, out);
}

// round 13
// speedup vs baseline: 1.2922x; 1.2922x over previous
#include <cuda_runtime.h>

// S4D via Vandermonde factorization as a per-h GEMM on tensor cores:
//   l = 64q + r;  out[h, 64q+r] = sum_n Re(u_n W_n^q w_n^r),  W = w^64
//   = sum_k A[q,k]*B[k,r],  k = 2n+{0,1}:
//     A[q,2n] = Re(u W^q), A[q,2n+1] = -Im(u W^q)
//     B[2n,r] = Re(w^r),   B[2n+1,r] =  Im(w^r)
// M=N=K=64 per h, computed with mma.sync.m16n8k8 tf32 using the 3xtf32 split
// (ah*bh + ah*bl + al*bh) for fp32-grade accuracy. B stored transposed
// Bt[r][k] so the col-major B-fragment loads are conflict-free (stride 68).

#define HH      1024
#define NH      32
#define LL      4096
#define THREADS 128
#define ASTR    68
#define BSTR    68

#define TWO_PI      6.283185307179586f
#define INV_TWO_PI  0.15915494309189535f

__device__ __forceinline__ unsigned tf32_rna(float x) {
    unsigned r;
    asm("cvt.rna.tf32.f32 %0, %1;" : "=r"(r) : "f"(x));
    return r;
}

#define MMA_TF32(C, A0, A1, A2, A3, B0, B1)                                  \
    asm("mma.sync.aligned.m16n8k8.row.col.f32.tf32.tf32.f32 "                \
        "{%0,%1,%2,%3}, {%4,%5,%6,%7}, {%8,%9}, {%0,%1,%2,%3};"              \
        : "+f"((C)[0]), "+f"((C)[1]), "+f"((C)[2]), "+f"((C)[3])             \
        : "r"(A0), "r"(A1), "r"(A2), "r"(A3), "r"(B0), "r"(B1))

__global__ __launch_bounds__(THREADS)
void s4d_kernel(const float* __restrict__ C_param,     // (H, 32, 2)
                const float* __restrict__ log_dt,      // (H,)
                const float* __restrict__ log_A_real,  // (H, 32)
                const float* __restrict__ A_imag,      // (H, 32)
                float* __restrict__ out)               // (H, L)
{
    __shared__ float A_s[64][ASTR];   // A[q][k]
    __shared__ float B_s[64][BSTR];   // Bt[r][k]  (B transposed)
    __shared__ float s_re[NH], s_turn[NH], s_wr[NH], s_wi[NH];
    __shared__ float s_ur[NH], s_ui[NH], s_Wr[NH], s_Wi[NH];

    const int h   = blockIdx.x;
    const int tid = threadIdx.x;

    // ---- per-(h,n) parameters (one warp; accurate libm) ----
    if (tid < NH) {
        const int n  = tid;
        const int hn = h * NH + n;
        float dt = expf(log_dt[h]);
        float Ar = -expf(log_A_real[hn]);
        float Ai = A_imag[hn];
        float re = Ar * dt;                          // Re(dtA) (<0)
        float im = Ai * dt;                          // Im(dtA)
        float er = expf(re);
        float si, co; sincosf(im, &si, &co);
        float wr = er * co, wi = er * si;            // w = exp(dtA)
        // u = 2*C*(w-1)/A
        float numr = wr - 1.0f, numi = wi;
        float invd = 1.0f / fmaf(Ar, Ar, Ai * Ai);
        float tr = (numr * Ar + numi * Ai) * invd;
        float ti = (numi * Ar - numr * Ai) * invd;
        float Cr = C_param[2 * hn + 0];
        float Ci = C_param[2 * hn + 1];
        float ur = 2.0f * (Cr * tr - Ci * ti);
        float ui = 2.0f * (Cr * ti + Ci * tr);
        float turn = im * INV_TWO_PI;
        // W = w^64 via turn trick
        float amp64 = expf(64.0f * re);
        float t64   = turn * 64.0f;
        float f64   = t64 - truncf(t64);
        float s64, c64; __sincosf(f64 * TWO_PI, &s64, &c64);
        s_re[n]   = re;   s_turn[n] = turn;
        s_wr[n]   = wr;   s_wi[n]   = wi;
        s_ur[n]   = ur;   s_ui[n]   = ui;
        s_Wr[n]   = amp64 * c64;  s_Wi[n] = amp64 * s64;
    }
    __syncthreads();

    // ---- generate A and Bt tiles: thread (n = tid>>2, j = tid&3) ----
    {
        const int gn = tid >> 2;          // n : 0..31
        const int gj = tid & 3;           // 16-element chunk
        const float re = s_re[gn], tn = s_turn[gn];

        // Bt[r][2n..2n+1] = (Re(w^r), Im(w^r)) for r = 16j..16j+15
        {
            const float wr = s_wr[gn], wi = s_wi[gn];
            float r0f  = (float)(16 * gj);
            float amp  = __expf(re * r0f);
            float turns = tn * r0f;
            float frac  = turns - truncf(turns);
            float si, co; __sincosf(frac * TWO_PI, &si, &co);
            float zr = amp * co, zi = amp * si;
            #pragma unroll
            for (int i = 0; i < 16; i++) {
                *reinterpret_cast<float2*>(&B_s[16 * gj + i][2 * gn]) =
                    make_float2(zr, zi);
                float nzr = zr * wr - zi * wi;
                float nzi = zr * wi + zi * wr;
                zr = nzr; zi = nzi;
            }
        }
        // A[q][2n..2n+1] = (Re(u W^q), -Im(u W^q)) for q = 16j..16j+15
        {
            const float Wr = s_Wr[gn], Wi = s_Wi[gn];
            const float ur = s_ur[gn], ui = s_ui[gn];
            float l0f  = (float)(1024 * gj);          // 64 * 16j
            float amp  = __expf(re * l0f);
            float turns = tn * l0f;
            float frac  = turns - truncf(turns);
            float si, co; __sincosf(frac * TWO_PI, &si, &co);
            float zr = amp * co, zi = amp * si;       // w^{64*16j}
            float pr = ur * zr - ui * zi;
            float pi = ur * zi + ui * zr;
            #pragma unroll
            for (int i = 0; i < 16; i++) {
                *reinterpret_cast<float2*>(&A_s[16 * gj + i][2 * gn]) =
                    make_float2(pr, -pi);
                float npr = pr * Wr - pi * Wi;
                float npi = pr * Wi + pi * Wr;
                pr = npr; pi = npi;
            }
        }
    }
    __syncthreads();

    // ---- tensor-core GEMM: each warp owns one 16-row m-tile ----
    const int warp = tid >> 5;
    const int lane = tid & 31;
    const int g = lane >> 2;              // groupID (0..7)
    const int t = lane & 3;               // thread-in-group (0..3)
    const int qrow = warp * 16 + g;

    float acc[8][4];
    #pragma unroll
    for (int nt = 0; nt < 8; nt++)
        #pragma unroll
        for (int i = 0; i < 4; i++) acc[nt][i] = 0.0f;

    #pragma unroll 1
    for (int kt = 0; kt < 8; kt++) {
        const int kc = kt * 8 + t;
        // A fragment (m16 x k8), row-major
        float a0 = A_s[qrow][kc],     a1 = A_s[qrow + 8][kc];
        float a2 = A_s[qrow][kc + 4], a3 = A_s[qrow + 8][kc + 4];
        unsigned ah0 = tf32_rna(a0), ah1 = tf32_rna(a1);
        unsigned ah2 = tf32_rna(a2), ah3 = tf32_rna(a3);
        unsigned al0 = __float_as_uint(a0 - __uint_as_float(ah0));
        unsigned al1 = __float_as_uint(a1 - __uint_as_float(ah1));
        unsigned al2 = __float_as_uint(a2 - __uint_as_float(ah2));
        unsigned al3 = __float_as_uint(a3 - __uint_as_float(ah3));

        #pragma unroll
        for (int nt = 0; nt < 8; nt++) {
            // B fragment (k8 x n8), col-major: B[k][n] = Bt[n][k]
            const int nrow = nt * 8 + g;
            float b0 = B_s[nrow][kc];          // k = kc
            float b1 = B_s[nrow][kc + 4];      // k = kc + 4
            unsigned bh0 = tf32_rna(b0), bh1 = tf32_rna(b1);
            unsigned bl0 = __float_as_uint(b0 - __uint_as_float(bh0));
            unsigned bl1 = __float_as_uint(b1 - __uint_as_float(bh1));

            MMA_TF32(acc[nt], ah0, ah1, ah2, ah3, bh0, bh1);
            MMA_TF32(acc[nt], ah0, ah1, ah2, ah3, bl0, bl1);
            MMA_TF32(acc[nt], al0, al1, al2, al3, bh0, bh1);
        }
    }

    // ---- epilogue: D fragment -> out[h, 64*q + r] ----
    float* obase = out + (size_t)h * LL;
    #pragma unroll
    for (int nt = 0; nt < 8; nt++) {
        const int r = nt * 8 + 2 * t;
        *reinterpret_cast<float2*>(&obase[qrow * 64 + r]) =
            make_float2(acc[nt][0], acc[nt][1]);
        *reinterpret_cast<float2*>(&obase[(qrow + 8) * 64 + r]) =
            make_float2(acc[nt][2], acc[nt][3]);
    }
}

extern "C" void kernel_launch(void* const* d_in, const int* in_sizes, int n_in,
                              void* d_out, int out_size) {
    const float* C_param    = (const float*)d_in[0];
    const float* log_dt     = (const float*)d_in[1];
    const float* log_A_real = (const float*)d_in[2];
    const float* A_imag     = (const float*)d_in[3];
    float* out = (float*)d_out;

    s4d_kernel<<<HH, THREADS>>>(C_param, log_dt, log_A_real, A_imag, out);
}

// round 14
// speedup vs baseline: 1.4459x; 1.1189x over previous
#include <cuda_runtime.h>

// S4D via Vandermonde factorization as a per-h GEMM on tensor cores:
//   l = 64q + r;  out[h, 64q+r] = sum_k A[q,k]*B[k,r],  k = 2n+{0,1}:
//     A[q,2n] = Re(u W^q), A[q,2n+1] = -Im(u W^q)   (W = w^64)
//     B[2n,r] = Re(w^r),   B[2n+1,r] =  Im(w^r)
// mma.sync.m16n8k16 bf16 with 3-product split (ah*bh + ah*bl + al*bh).
// hi/lo bf16 split is done ONCE in the generation phase and stored packed
// (bf16x2 per k-pair) so the main loop is pure LDS.32 + HMMA.

#define HH      1024
#define NH      32
#define LL      4096
#define THREADS 128
#define KP      32          // k-pairs (K=64 -> 32 bf16x2 words per row)
#define PSTR    36          // row stride in uint (bank-safe: 36g+t -> 4g+t)

#define TWO_PI      6.283185307179586f
#define INV_TWO_PI  0.15915494309189535f

// pack(hi, lo): result.hi16 = bf16_rn(hi), result.lo16 = bf16_rn(lo)
__device__ __forceinline__ unsigned pack_bf16x2(float hi, float lo) {
    unsigned r;
    asm("cvt.rn.bf16x2.f32 %0, %1, %2;" : "=r"(r) : "f"(hi), "f"(lo));
    return r;
}

#define MMA_BF16(C, A0, A1, A2, A3, B0, B1)                                  \
    asm("mma.sync.aligned.m16n8k16.row.col.f32.bf16.bf16.f32 "               \
        "{%0,%1,%2,%3}, {%4,%5,%6,%7}, {%8,%9}, {%0,%1,%2,%3};"              \
        : "+f"((C)[0]), "+f"((C)[1]), "+f"((C)[2]), "+f"((C)[3])             \
        : "r"(A0), "r"(A1), "r"(A2), "r"(A3), "r"(B0), "r"(B1))

__global__ __launch_bounds__(THREADS)
void s4d_kernel(const float* __restrict__ C_param,     // (H, 32, 2)
                const float* __restrict__ log_dt,      // (H,)
                const float* __restrict__ log_A_real,  // (H, 32)
                const float* __restrict__ A_imag,      // (H, 32)
                float* __restrict__ out)               // (H, L)
{
    __shared__ unsigned A_hi[64][PSTR], A_lo[64][PSTR];   // A[q][k-pair]
    __shared__ unsigned B_hi[64][PSTR], B_lo[64][PSTR];   // Bt[r][k-pair]
    __shared__ float s_re[NH], s_turn[NH], s_wr[NH], s_wi[NH];
    __shared__ float s_ur[NH], s_ui[NH], s_Wr[NH], s_Wi[NH];

    const int h   = blockIdx.x;
    const int tid = threadIdx.x;

    // ---- per-(h,n) parameters (one warp; accurate libm) ----
    if (tid < NH) {
        const int n  = tid;
        const int hn = h * NH + n;
        float dt = expf(log_dt[h]);
        float Ar = -expf(log_A_real[hn]);
        float Ai = A_imag[hn];
        float re = Ar * dt;                          // Re(dtA) (<0)
        float im = Ai * dt;                          // Im(dtA)
        float er = expf(re);
        float si, co; sincosf(im, &si, &co);
        float wr = er * co, wi = er * si;            // w = exp(dtA)
        // u = 2*C*(w-1)/A
        float numr = wr - 1.0f, numi = wi;
        float invd = 1.0f / fmaf(Ar, Ar, Ai * Ai);
        float tr = (numr * Ar + numi * Ai) * invd;
        float ti = (numi * Ar - numr * Ai) * invd;
        float Cr = C_param[2 * hn + 0];
        float Ci = C_param[2 * hn + 1];
        float ur = 2.0f * (Cr * tr - Ci * ti);
        float ui = 2.0f * (Cr * ti + Ci * tr);
        float turn = im * INV_TWO_PI;
        // W = w^64 via turn trick
        float amp64 = expf(64.0f * re);
        float t64   = turn * 64.0f;
        float f64   = t64 - truncf(t64);
        float s64, c64; __sincosf(f64 * TWO_PI, &s64, &c64);
        s_re[n]   = re;   s_turn[n] = turn;
        s_wr[n]   = wr;   s_wi[n]   = wi;
        s_ur[n]   = ur;   s_ui[n]   = ui;
        s_Wr[n]   = amp64 * c64;  s_Wi[n] = amp64 * s64;
    }
    __syncthreads();

    // ---- generate A / Bt tiles with bf16 hi/lo split, packed per k-pair ----
    // thread (gn = tid>>2 : n index, gj = tid&3 : 16-row chunk)
    {
        const int gn = tid >> 2;
        const int gj = tid & 3;
        const float re = s_re[gn], tn = s_turn[gn];

        // Bt[r][pair gn] = (lo=Re(w^r), hi=Im(w^r)) for r = 16gj..16gj+15
        {
            const float wr = s_wr[gn], wi = s_wi[gn];
            float r0f  = (float)(16 * gj);
            float amp  = __expf(re * r0f);
            float turns = tn * r0f;
            float frac  = turns - truncf(turns);
            float si, co; __sincosf(frac * TWO_PI, &si, &co);
            float zr = amp * co, zi = amp * si;
            #pragma unroll
            for (int i = 0; i < 16; i++) {
                unsigned hp = pack_bf16x2(zi, zr);
                float rh_lo = __uint_as_float(hp << 16);
                float rh_hi = __uint_as_float(hp & 0xFFFF0000u);
                unsigned lp = pack_bf16x2(zi - rh_hi, zr - rh_lo);
                B_hi[16 * gj + i][gn] = hp;
                B_lo[16 * gj + i][gn] = lp;
                float nzr = zr * wr - zi * wi;
                float nzi = zr * wi + zi * wr;
                zr = nzr; zi = nzi;
            }
        }
        // A[q][pair gn] = (lo=Re(uW^q), hi=-Im(uW^q)) for q = 16gj..16gj+15
        {
            const float Wr = s_Wr[gn], Wi = s_Wi[gn];
            const float ur = s_ur[gn], ui = s_ui[gn];
            float l0f  = (float)(1024 * gj);          // 64 * 16gj
            float amp  = __expf(re * l0f);
            float turns = tn * l0f;
            float frac  = turns - truncf(turns);
            float si, co; __sincosf(frac * TWO_PI, &si, &co);
            float zr = amp * co, zi = amp * si;       // w^{64*16gj}
            float pr = ur * zr - ui * zi;
            float pi = ur * zi + ui * zr;
            #pragma unroll
            for (int i = 0; i < 16; i++) {
                float npi = -pi;
                unsigned hp = pack_bf16x2(npi, pr);
                float rh_lo = __uint_as_float(hp << 16);
                float rh_hi = __uint_as_float(hp & 0xFFFF0000u);
                unsigned lp = pack_bf16x2(npi - rh_hi, pr - rh_lo);
                A_hi[16 * gj + i][gn] = hp;
                A_lo[16 * gj + i][gn] = lp;
                float tpr = pr * Wr - pi * Wi;
                float tpi = pr * Wi + pi * Wr;
                pr = tpr; pi = tpi;
            }
        }
    }
    __syncthreads();

    // ---- tensor-core GEMM: warp owns 16 q-rows; bf16 m16n8k16, 3 products ----
    const int warp = tid >> 5;
    const int lane = tid & 31;
    const int g = lane >> 2;              // groupID (0..7)
    const int t = lane & 3;               // thread-in-group (0..3)
    const int qrow = warp * 16 + g;

    float acc[8][4];
    #pragma unroll
    for (int nt = 0; nt < 8; nt++)
        #pragma unroll
        for (int i = 0; i < 4; i++) acc[nt][i] = 0.0f;

    #pragma unroll 1
    for (int kt = 0; kt < 4; kt++) {      // K = 64 -> 4 tiles of k16
        const int kp = 8 * kt + t;        // k-pair index for this thread
        // A fragment: a0=(g, k2t) a1=(g+8, k2t) a2=(g, k2t+8) a3=(g+8, k2t+8)
        unsigned ah0 = A_hi[qrow][kp],     ah1 = A_hi[qrow + 8][kp];
        unsigned ah2 = A_hi[qrow][kp + 4], ah3 = A_hi[qrow + 8][kp + 4];
        unsigned al0 = A_lo[qrow][kp],     al1 = A_lo[qrow + 8][kp];
        unsigned al2 = A_lo[qrow][kp + 4], al3 = A_lo[qrow + 8][kp + 4];

        #pragma unroll
        for (int nt = 0; nt < 8; nt++) {
            const int nrow = nt * 8 + g;
            unsigned bh0 = B_hi[nrow][kp], bh1 = B_hi[nrow][kp + 4];
            unsigned bl0 = B_lo[nrow][kp], bl1 = B_lo[nrow][kp + 4];

            MMA_BF16(acc[nt], ah0, ah1, ah2, ah3, bh0, bh1);
            MMA_BF16(acc[nt], ah0, ah1, ah2, ah3, bl0, bl1);
            MMA_BF16(acc[nt], al0, al1, al2, al3, bh0, bh1);
        }
    }

    // ---- epilogue: D fragment -> out[h, 64*q + r] ----
    float* obase = out + (size_t)h * LL;
    #pragma unroll
    for (int nt = 0; nt < 8; nt++) {
        const int r = nt * 8 + 2 * t;
        *reinterpret_cast<float2*>(&obase[qrow * 64 + r]) =
            make_float2(acc[nt][0], acc[nt][1]);
        *reinterpret_cast<float2*>(&obase[(qrow + 8) * 64 + r]) =
            make_float2(acc[nt][2], acc[nt][3]);
    }
}

extern "C" void kernel_launch(void* const* d_in, const int* in_sizes, int n_in,
                              void* d_out, int out_size) {
    const float* C_param    = (const float*)d_in[0];
    const float* log_dt     = (const float*)d_in[1];
    const float* log_A_real = (const float*)d_in[2];
    const float* A_imag     = (const float*)d_in[3];
    float* out = (float*)d_out;

    s4d_kernel<<<HH, THREADS>>>(C_param, log_dt, log_A_real, A_imag, out);
}

// round 15
// speedup vs baseline: 1.4489x; 1.0021x over previous
#include <cuda_runtime.h>

// S4D via Vandermonde factorization as a per-h GEMM on tensor cores:
//   l = 64q + r;  out[h, 64q+r] = sum_k A[q,k]*B[k,r],  k = 2n+{0,1}:
//     A[q,2n] = Re(u W^q), A[q,2n+1] = -Im(u W^q)   (W = w^64)
//     B[2n,r] = Re(w^r),   B[2n+1,r] =  Im(w^r)
// mma.sync.m16n8k16 bf16, 3-product split (ah*bh + ah*bl + al*bh), hi/lo
// split precomputed and stored INTERLEAVED as uint2 so every fragment word
// is one LDS.64. 256 threads: warp=(mw,nw) owns a 16q x 32r tile -> 48 MMA
// + 48 LDS.64 per thread; gen recurrences are 8 steps per thread.

#define HH      1024
#define NH      32
#define LL      4096
#define THREADS 256
#define PSTR    36          // row stride in uint2 (4B-stride 72 = 8 mod 32)

#define TWO_PI      6.283185307179586f
#define INV_TWO_PI  0.15915494309189535f

// pack(hi, lo): result.hi16 = bf16_rn(hi), result.lo16 = bf16_rn(lo)
__device__ __forceinline__ unsigned pack_bf16x2(float hi, float lo) {
    unsigned r;
    asm("cvt.rn.bf16x2.f32 %0, %1, %2;" : "=r"(r) : "f"(hi), "f"(lo));
    return r;
}

#define MMA_BF16(C, A0, A1, A2, A3, B0, B1)                                  \
    asm("mma.sync.aligned.m16n8k16.row.col.f32.bf16.bf16.f32 "               \
        "{%0,%1,%2,%3}, {%4,%5,%6,%7}, {%8,%9}, {%0,%1,%2,%3};"              \
        : "+f"((C)[0]), "+f"((C)[1]), "+f"((C)[2]), "+f"((C)[3])             \
        : "r"(A0), "r"(A1), "r"(A2), "r"(A3), "r"(B0), "r"(B1))

__global__ __launch_bounds__(THREADS)
void s4d_kernel(const float* __restrict__ C_param,     // (H, 32, 2)
                const float* __restrict__ log_dt,      // (H,)
                const float* __restrict__ log_A_real,  // (H, 32)
                const float* __restrict__ A_imag,      // (H, 32)
                float* __restrict__ out)               // (H, L)
{
    __shared__ uint2 A_s[64][PSTR];   // A[q][k-pair] : x=hi(bf16x2), y=lo
    __shared__ uint2 B_s[64][PSTR];   // Bt[r][k-pair]
    __shared__ float s_re[NH], s_turn[NH], s_wr[NH], s_wi[NH];
    __shared__ float s_ur[NH], s_ui[NH], s_Wr[NH], s_Wi[NH];

    const int h   = blockIdx.x;
    const int tid = threadIdx.x;

    // ---- per-(h,n) parameters (one warp; accurate libm) ----
    if (tid < NH) {
        const int n  = tid;
        const int hn = h * NH + n;
        float dt = expf(log_dt[h]);
        float Ar = -expf(log_A_real[hn]);
        float Ai = A_imag[hn];
        float re = Ar * dt;                          // Re(dtA) (<0)
        float im = Ai * dt;                          // Im(dtA)
        float er = expf(re);
        float si, co; sincosf(im, &si, &co);
        float wr = er * co, wi = er * si;            // w = exp(dtA)
        // u = 2*C*(w-1)/A
        float numr = wr - 1.0f, numi = wi;
        float invd = 1.0f / fmaf(Ar, Ar, Ai * Ai);
        float tr = (numr * Ar + numi * Ai) * invd;
        float ti = (numi * Ar - numr * Ai) * invd;
        float Cr = C_param[2 * hn + 0];
        float Ci = C_param[2 * hn + 1];
        float ur = 2.0f * (Cr * tr - Ci * ti);
        float ui = 2.0f * (Cr * ti + Ci * tr);
        float turn = im * INV_TWO_PI;
        // W = w^64 via turn trick
        float amp64 = expf(64.0f * re);
        float t64   = turn * 64.0f;
        float f64   = t64 - truncf(t64);
        float s64, c64; __sincosf(f64 * TWO_PI, &s64, &c64);
        s_re[n]   = re;   s_turn[n] = turn;
        s_wr[n]   = wr;   s_wi[n]   = wi;
        s_ur[n]   = ur;   s_ui[n]   = ui;
        s_Wr[n]   = amp64 * c64;  s_Wi[n] = amp64 * s64;
    }
    __syncthreads();

    // ---- generate A / Bt tiles: thread (gn = tid&31 : n, gw = tid>>5 : chunk) ----
    // 8 rows per thread; a warp writes full 32-column rows (coalesced uint2).
    {
        const int gn = tid & 31;
        const int gw = tid >> 5;
        const float re = s_re[gn], tn = s_turn[gn];

        // Bt[r][gn] for r = 8gw .. 8gw+7 : (lo=Re(w^r), hi=Im(w^r))
        {
            const float wr = s_wr[gn], wi = s_wi[gn];
            float r0f  = (float)(8 * gw);
            float amp  = __expf(re * r0f);
            float turns = tn * r0f;
            float frac  = turns - truncf(turns);
            float si, co; __sincosf(frac * TWO_PI, &si, &co);
            float zr = amp * co, zi = amp * si;
            #pragma unroll
            for (int i = 0; i < 8; i++) {
                unsigned hp = pack_bf16x2(zi, zr);
                float rh_lo = __uint_as_float(hp << 16);
                float rh_hi = __uint_as_float(hp & 0xFFFF0000u);
                unsigned lp = pack_bf16x2(zi - rh_hi, zr - rh_lo);
                B_s[8 * gw + i][gn] = make_uint2(hp, lp);
                float nzr = zr * wr - zi * wi;
                float nzi = zr * wi + zi * wr;
                zr = nzr; zi = nzi;
            }
        }
        // A[q][gn] for q = 8gw .. 8gw+7 : (lo=Re(uW^q), hi=-Im(uW^q))
        {
            const float Wr = s_Wr[gn], Wi = s_Wi[gn];
            const float ur = s_ur[gn], ui = s_ui[gn];
            float l0f  = (float)(512 * gw);           // 64 * 8gw
            float amp  = __expf(re * l0f);
            float turns = tn * l0f;
            float frac  = turns - truncf(turns);
            float si, co; __sincosf(frac * TWO_PI, &si, &co);
            float zr = amp * co, zi = amp * si;       // w^{64*8gw}
            float pr = ur * zr - ui * zi;
            float pi = ur * zi + ui * zr;
            #pragma unroll
            for (int i = 0; i < 8; i++) {
                float npi = -pi;
                unsigned hp = pack_bf16x2(npi, pr);
                float rh_lo = __uint_as_float(hp << 16);
                float rh_hi = __uint_as_float(hp & 0xFFFF0000u);
                unsigned lp = pack_bf16x2(npi - rh_hi, pr - rh_lo);
                A_s[8 * gw + i][gn] = make_uint2(hp, lp);
                float tpr = pr * Wr - pi * Wi;
                float tpi = pr * Wi + pi * Wr;
                pr = tpr; pi = tpi;
            }
        }
    }
    __syncthreads();

    // ---- tensor-core GEMM: 8 warps = (mw: 16 q-rows) x (nw: 4 n-tiles) ----
    const int warp = tid >> 5;
    const int mw   = warp & 3;
    const int nw   = warp >> 2;
    const int lane = tid & 31;
    const int g = lane >> 2;              // groupID (0..7)
    const int t = lane & 3;               // thread-in-group (0..3)
    const int qrow = mw * 16 + g;

    float acc[4][4];
    #pragma unroll
    for (int j = 0; j < 4; j++)
        #pragma unroll
        for (int i = 0; i < 4; i++) acc[j][i] = 0.0f;

    #pragma unroll 1
    for (int kt = 0; kt < 4; kt++) {      // K = 64 -> 4 tiles of k16
        const int kp = 8 * kt + t;        // k-pair index for this thread
        uint2 va0 = A_s[qrow][kp];
        uint2 va1 = A_s[qrow + 8][kp];
        uint2 va2 = A_s[qrow][kp + 4];
        uint2 va3 = A_s[qrow + 8][kp + 4];

        #pragma unroll
        for (int j = 0; j < 4; j++) {
            const int nrow = (nw * 4 + j) * 8 + g;
            uint2 vb0 = B_s[nrow][kp];
            uint2 vb1 = B_s[nrow][kp + 4];

            MMA_BF16(acc[j], va0.x, va1.x, va2.x, va3.x, vb0.x, vb1.x);
            MMA_BF16(acc[j], va0.x, va1.x, va2.x, va3.x, vb0.y, vb1.y);
            MMA_BF16(acc[j], va0.y, va1.y, va2.y, va3.y, vb0.x, vb1.x);
        }
    }

    // ---- epilogue: D fragments -> out[h, 64*q + r] ----
    float* obase = out + (size_t)h * LL;
    #pragma unroll
    for (int j = 0; j < 4; j++) {
        const int r = (nw * 4 + j) * 8 + 2 * t;
        *reinterpret_cast<float2*>(&obase[qrow * 64 + r]) =
            make_float2(acc[j][0], acc[j][1]);
        *reinterpret_cast<float2*>(&obase[(qrow + 8) * 64 + r]) =
            make_float2(acc[j][2], acc[j][3]);
    }
}

extern "C" void kernel_launch(void* const* d_in, const int* in_sizes, int n_in,
                              void* d_out, int out_size) {
    const float* C_param    = (const float*)d_in[0];
    const float* log_dt     = (const float*)d_in[1];
    const float* log_A_real = (const float*)d_in[2];
    const float* A_imag     = (const float*)d_in[3];
    float* out = (float*)d_out;

    s4d_kernel<<<HH, THREADS>>>(C_param, log_dt, log_A_real, A_imag, out);
}